// round 12
// baseline (speedup 1.0000x reference)
#include <cuda_runtime.h>
#include <cuda_fp16.h>
#include <cstdint>

#define B_DIM   1024
#define N_IN    512
#define HID     64
#define N_OUT   256
#define QKV_N   (HID * N_OUT)   // 16384

// ----------------------------- PTX helpers ----------------------------------
__device__ __forceinline__ void mma16816(float* c, const uint32_t* a, const uint32_t* b) {
    asm volatile(
        "mma.sync.aligned.m16n8k16.row.col.f32.f16.f16.f32 "
        "{%0,%1,%2,%3}, {%4,%5,%6,%7}, {%8,%9}, {%0,%1,%2,%3};"
        : "+f"(c[0]), "+f"(c[1]), "+f"(c[2]), "+f"(c[3])
        : "r"(a[0]), "r"(a[1]), "r"(a[2]), "r"(a[3]), "r"(b[0]), "r"(b[1]));
}
__device__ __forceinline__ uint32_t packh2(float x, float y) {
    __half2 h = __floats2half2_rn(x, y);
    return *(uint32_t*)&h;
}
__device__ __forceinline__ uint32_t smem_u32(const void* p) {
    uint32_t a;
    asm("{ .reg .u64 t; cvta.to.shared.u64 t, %1; cvt.u32.u64 %0, t; }" : "=r"(a) : "l"(p));
    return a;
}
__device__ __forceinline__ void ldmx4(uint32_t* r, uint32_t addr) {
    asm volatile("ldmatrix.sync.aligned.m8n8.x4.shared.b16 {%0,%1,%2,%3}, [%4];"
                 : "=r"(r[0]), "=r"(r[1]), "=r"(r[2]), "=r"(r[3]) : "r"(addr));
}
__device__ __forceinline__ void ldmx2t(uint32_t* r, uint32_t addr) {
    asm volatile("ldmatrix.sync.aligned.m8n8.x2.trans.shared.b16 {%0,%1}, [%2];"
                 : "=r"(r[0]), "=r"(r[1]) : "r"(addr));
}
__device__ __forceinline__ void cpa16(uint32_t dst, const void* src) {
    asm volatile("{ .reg .u64 g; cvta.to.global.u64 g, %1; "
                 "cp.async.cg.shared.global [%0], [g], 16; }"
                 :: "r"(dst), "l"(src));
}
#define CP_COMMIT() asm volatile("cp.async.commit_group;" ::: "memory")
#define CP_WAIT1()  asm volatile("cp.async.wait_group 1;" ::: "memory")
#define CP_WAIT0()  asm volatile("cp.async.wait_group 0;" ::: "memory")

// -------------------- scratch (device globals; no allocation) ---------------
__device__ __half g_h[B_DIM * N_IN];              // ln output fp16
__device__ __half g_wt[3ull * QKV_N * N_IN];      // W^T [w][n][k] fp16
__device__ __half g_qh[(size_t)B_DIM * QKV_N];    // (q+bq)*0.125
__device__ __half g_kh[(size_t)B_DIM * QKV_N];
__device__ __half g_vh[(size_t)B_DIM * QKV_N];
__device__ __half g_oh[(size_t)B_DIM * QKV_N];    // normalized attention out
__device__ __half g_wot[N_OUT * HID];             // Wo^T [n][d]

// ------------------------------ LayerNorm -> fp16 ---------------------------
__global__ __launch_bounds__(128) void ln_kernel(const float* __restrict__ x,
                                                 const float* __restrict__ gamma,
                                                 const float* __restrict__ beta) {
    __shared__ float ssum[4], ssq[4];
    const int b   = blockIdx.x;
    const int tid = threadIdx.x;
    const float4 v = ((const float4*)(x + (size_t)b * N_IN))[tid];
    float s = v.x + v.y + v.z + v.w;
    float q = v.x * v.x + v.y * v.y + v.z * v.z + v.w * v.w;
    #pragma unroll
    for (int o = 16; o > 0; o >>= 1) {
        s += __shfl_xor_sync(0xffffffffu, s, o);
        q += __shfl_xor_sync(0xffffffffu, q, o);
    }
    if ((tid & 31) == 0) { ssum[tid >> 5] = s; ssq[tid >> 5] = q; }
    __syncthreads();
    s = ssum[0] + ssum[1] + ssum[2] + ssum[3];
    q = ssq[0] + ssq[1] + ssq[2] + ssq[3];
    const float mu   = s * (1.0f / N_IN);
    const float var  = q * (1.0f / N_IN) - mu * mu;
    const float rstd = rsqrtf(var + 1e-5f);
    const float4 g  = ((const float4*)gamma)[tid];
    const float4 be = ((const float4*)beta)[tid];
    uint2 o;
    o.x = packh2((v.x - mu) * rstd * g.x + be.x, (v.y - mu) * rstd * g.y + be.y);
    o.y = packh2((v.z - mu) * rstd * g.z + be.z, (v.w - mu) * rstd * g.w + be.w);
    *(uint2*)(g_h + (size_t)b * N_IN + 4 * tid) = o;
}

// -------- transpose W: fp32 [K=512][N=16384] -> fp16 [N][K] -----------------
__global__ __launch_bounds__(256) void wsplit(const float* __restrict__ Wq,
                                              const float* __restrict__ Wk,
                                              const float* __restrict__ Wv) {
    const float* W = (blockIdx.z == 0) ? Wq : (blockIdx.z == 1) ? Wk : Wv;
    __shared__ float s[64][33];
    const int tid = threadIdx.x;
    const int n0 = blockIdx.x * 32, k0 = blockIdx.y * 64;
    #pragma unroll
    for (int i = 0; i < 8; i++) {
        const int k = i * 8 + (tid >> 5);
        const int n = tid & 31;
        s[k][n] = W[(size_t)(k0 + k) * QKV_N + n0 + n];
    }
    __syncthreads();
    const int n  = tid >> 3;
    const int c8 = (tid & 7) * 8;
    __half h8[8];
    #pragma unroll
    for (int j = 0; j < 8; j++) h8[j] = __float2half_rn(s[c8 + j][n]);
    *(uint4*)(g_wt + ((size_t)blockIdx.z * QKV_N + n0 + n) * N_IN + k0 + c8) = *(uint4*)h8;
}

// ----------------------- Wo^T fp16 precompute -------------------------------
__global__ __launch_bounds__(256) void wot_prep(const float* __restrict__ Wo) {
    const int idx = blockIdx.x * 256 + threadIdx.x;
    const int n = idx >> 6, d = idx & 63;
    g_wot[idx] = __float2half_rn(Wo[d * N_OUT + n]);
}

// ---------- QKV GEMM (R8 best): 128x128 CTA, 4 warps @ 64x64, 3-stage -------
#define GST   72                                  // smem row stride (halfs)
#define STAGE (256 * GST)                         // A(128) + B(128) rows
#define GEMM_SMEM (3 * STAGE * 2)                 // 110592 bytes

__global__ __launch_bounds__(128, 2) void gemm_tc(const float* __restrict__ bq,
                                                  const float* __restrict__ bk,
                                                  const float* __restrict__ bv) {
    extern __shared__ __half sh[];
    const uint32_t sbase = smem_u32(sh);
    const int tid = threadIdx.x;
    const int lane = tid & 31, wid = tid >> 5;
    const int g = lane >> 2, t = lane & 3;
    const int wm = wid >> 1, wn = wid & 1;        // 2m x 2n warps, 64x64 tile
    const int m0 = blockIdx.x * 128;
    const int n0 = blockIdx.y * 128;
    const int w  = blockIdx.z;
    const float* bias = (w == 0) ? bq : (w == 1) ? bk : bv;
    __half* outh = (w == 0) ? g_qh : (w == 1) ? g_kh : g_vh;
    const __half* wt = g_wt + (size_t)w * QKV_N * N_IN;

    float acc[4][8][4];
    #pragma unroll
    for (int i = 0; i < 4; i++)
        #pragma unroll
        for (int j = 0; j < 8; j++)
            #pragma unroll
            for (int q = 0; q < 4; q++) acc[i][j][q] = 0.0f;

    auto load_chunk = [&](int c, int st) {
        const int kt = c * 64;
        const uint32_t s0 = sbase + st * STAGE * 2;
        #pragma unroll
        for (int l = 0; l < 8; l++) {
            const int i = l * 128 + tid;
            const int r = i >> 3, c8 = (i & 7) * 8;
            cpa16(s0 + (r * GST + c8) * 2, g_h + (size_t)(m0 + r) * N_IN + kt + c8);
        }
        #pragma unroll
        for (int l = 0; l < 8; l++) {
            const int i = l * 128 + tid;
            const int r = i >> 3, c8 = (i & 7) * 8;
            cpa16(s0 + ((128 + r) * GST + c8) * 2, wt + (size_t)(n0 + r) * N_IN + kt + c8);
        }
    };

    const int aRow = wm * 64 + (lane & 15);
    const int aCol = (lane >> 4) * 8;
    const int bRow = 128 + wn * 64 + (lane & 7) + ((lane >> 4) & 1) * 8;
    const int bCol = ((lane >> 3) & 1) * 8;

    load_chunk(0, 0); CP_COMMIT();
    load_chunk(1, 1); CP_COMMIT();

    #pragma unroll 1
    for (int c = 0; c < 8; c++) {
        const int st = c % 3;
        if (c < 7) CP_WAIT1(); else CP_WAIT0();   // tail: drain fully
        __syncthreads();
        if (c + 2 < 8) { load_chunk(c + 2, (c + 2) % 3); CP_COMMIT(); }

        const uint32_t s0 = sbase + st * STAGE * 2;
        #pragma unroll
        for (int kk = 0; kk < 4; kk++) {
            const int kc = kk * 16;
            uint32_t ah[4][4], bh[4][4];
            #pragma unroll
            for (int mi = 0; mi < 4; mi++)
                ldmx4(ah[mi], s0 + ((aRow + mi * 16) * GST + kc + aCol) * 2);
            #pragma unroll
            for (int nb = 0; nb < 4; nb++)
                ldmx4(bh[nb], s0 + ((bRow + nb * 16) * GST + kc + bCol) * 2);
            #pragma unroll
            for (int mi = 0; mi < 4; mi++)
                #pragma unroll
                for (int nj = 0; nj < 8; nj++)
                    mma16816(acc[mi][nj], ah[mi], &bh[nj >> 1][(nj & 1) * 2]);
        }
    }

    const float scale = (w == 0) ? 0.125f : 1.0f;
    #pragma unroll
    for (int mi = 0; mi < 4; mi++) {
        const int r = m0 + wm * 64 + mi * 16 + g;
        #pragma unroll
        for (int nj = 0; nj < 8; nj++) {
            const int col = n0 + wn * 64 + nj * 8 + 2 * t;
            const float b0 = __ldg(bias + col), b1 = __ldg(bias + col + 1);
            *(uint32_t*)(outh + (size_t)r * QKV_N + col) =
                packh2((acc[mi][nj][0] + b0) * scale, (acc[mi][nj][1] + b1) * scale);
            *(uint32_t*)(outh + (size_t)(r + 8) * QKV_N + col) =
                packh2((acc[mi][nj][2] + b0) * scale, (acc[mi][nj][3] + b1) * scale);
        }
    }
}

// --------------- attention core: softmax(QK^T)V -> g_oh (fp16) --------------
// R6 mainloop; K,V staged via cp.async (V row-major, PV fragments via
// ldmatrix.x2.trans — mapping verified bit-identical in R10). Q from gmem.
#define AST 72
#define OFF_K  0
#define OFF_V  (256 * AST)
#define ATTN_SMEM (2 * 256 * AST * 2)

__global__ __launch_bounds__(256, 1) void attn_kernel(float* __restrict__ dummy) {
    extern __shared__ __half sh[];
    const uint32_t sbase = smem_u32(sh);
    __half* Ks = sh + OFF_K;

    const int b   = blockIdx.x;
    const int tid = threadIdx.x;
    const int lane = tid & 31, wid = tid >> 5;
    const int g = lane >> 2, t = lane & 3;
    const int rw0 = wid * 32;

    const __half* qg = g_qh + (size_t)b * QKV_N;
    const __half* kg = g_kh + (size_t)b * QKV_N;
    const __half* vg = g_vh + (size_t)b * QKV_N;

    #pragma unroll
    for (int l = 0; l < 8; l++) {
        const int i = l * 256 + tid;
        const int r = i >> 3, c8 = (i & 7) * 8;
        cpa16(sbase + (OFF_K + r * AST + c8) * 2, kg + r * HID + c8);
        cpa16(sbase + (OFF_V + r * AST + c8) * 2, vg + r * HID + c8);
    }
    CP_COMMIT();

    // Q A-fragments straight from gmem
    uint32_t aq[2][4][4];
    #pragma unroll
    for (int mi = 0; mi < 2; mi++) {
        const int r = rw0 + mi * 16 + g;
        #pragma unroll
        for (int kk = 0; kk < 4; kk++) {
            const int kc = kk * 16 + 2 * t;
            aq[mi][kk][0] = __ldg((const uint32_t*)(qg + r * HID + kc));
            aq[mi][kk][1] = __ldg((const uint32_t*)(qg + (r + 8) * HID + kc));
            aq[mi][kk][2] = __ldg((const uint32_t*)(qg + r * HID + kc + 8));
            aq[mi][kk][3] = __ldg((const uint32_t*)(qg + (r + 8) * HID + kc + 8));
        }
    }
    CP_WAIT0();
    __syncthreads();

    float oc[2][8][4];
    #pragma unroll
    for (int mi = 0; mi < 2; mi++)
        #pragma unroll
        for (int j = 0; j < 8; j++)
            #pragma unroll
            for (int q = 0; q < 4; q++) oc[mi][j][q] = 0.0f;
    float lp[2][2] = {{0.f, 0.f}, {0.f, 0.f}};

    const uint32_t vaddr = sbase + OFF_V * 2;

    #pragma unroll 1
    for (int c = 0; c < 4; c++) {
        float sc[2][8][4];
        #pragma unroll
        for (int mi = 0; mi < 2; mi++)
            #pragma unroll
            for (int j = 0; j < 8; j++)
                #pragma unroll
                for (int q = 0; q < 4; q++) sc[mi][j][q] = 0.0f;

        #pragma unroll
        for (int kk = 0; kk < 4; kk++) {
            const int kc = kk * 16 + 2 * t;
            #pragma unroll
            for (int j = 0; j < 8; j++) {
                uint32_t bk[2];
                const int kv = 64 * c + 8 * j + g;
                bk[0] = *(const uint32_t*)(Ks + kv * AST + kc);
                bk[1] = *(const uint32_t*)(Ks + kv * AST + kc + 8);
                mma16816(sc[0][j], aq[0][kk], bk);
                mma16816(sc[1][j], aq[1][kk], bk);
            }
        }

        uint32_t pa[2][4][4];
        #pragma unroll
        for (int mi = 0; mi < 2; mi++) {
            #pragma unroll
            for (int j = 0; j < 8; j++) {
                float e0 = __expf(sc[mi][j][0]);
                float e1 = __expf(sc[mi][j][1]);
                float e2 = __expf(sc[mi][j][2]);
                float e3 = __expf(sc[mi][j][3]);
                lp[mi][0] += e0 + e1;
                lp[mi][1] += e2 + e3;
                const int kk2 = j >> 1, hi = j & 1;
                pa[mi][kk2][hi * 2 + 0] = packh2(e0, e1);
                pa[mi][kk2][hi * 2 + 1] = packh2(e2, e3);
            }
        }

        #pragma unroll
        for (int kk2 = 0; kk2 < 4; kk2++) {
            const int kv0 = 64 * c + kk2 * 16;
            #pragma unroll
            for (int j2 = 0; j2 < 8; j2++) {
                uint32_t bv[2];
                ldmx2t(bv, vaddr + ((kv0 + (lane & 15)) * AST + 8 * j2) * 2);
                mma16816(oc[0][j2], pa[0][kk2], bv);
                mma16816(oc[1][j2], pa[1][kk2], bv);
            }
        }
    }

    #pragma unroll
    for (int mi = 0; mi < 2; mi++)
        #pragma unroll
        for (int h = 0; h < 2; h++) {
            float l = lp[mi][h];
            l += __shfl_xor_sync(0xffffffffu, l, 1);
            l += __shfl_xor_sync(0xffffffffu, l, 2);
            lp[mi][h] = 1.0f / l;
        }

    // pack normalized o to fp16 and store (33 MB total — cheap)
    __half* obh = g_oh + (size_t)b * QKV_N;
    #pragma unroll
    for (int mi = 0; mi < 2; mi++) {
        const int r = rw0 + mi * 16 + g;
        #pragma unroll
        for (int kk = 0; kk < 4; kk++) {
            const int j2a = 2 * kk, j2b = 2 * kk + 1;
            const int col = 16 * kk + 2 * t;
            *(uint32_t*)(obh + r * HID + col) =
                packh2(oc[mi][j2a][0] * lp[mi][0], oc[mi][j2a][1] * lp[mi][0]);
            *(uint32_t*)(obh + (r + 8) * HID + col) =
                packh2(oc[mi][j2a][2] * lp[mi][1], oc[mi][j2a][3] * lp[mi][1]);
            *(uint32_t*)(obh + r * HID + col + 8) =
                packh2(oc[mi][j2b][0] * lp[mi][0], oc[mi][j2b][1] * lp[mi][0]);
            *(uint32_t*)(obh + (r + 8) * HID + col + 8) =
                packh2(oc[mi][j2b][2] * lp[mi][1], oc[mi][j2b][3] * lp[mi][1]);
        }
    }
}

// ------------- streaming out-projection: out = -relu(o Wo + bo) -------------
// 1024 CTAs x 256 threads, 2 CTAs/SM. o fragments via __ldg (warp-private),
// Wo^T in smem. Write-bandwidth bound by design.
#define PROJ_SMEM (256 * AST * 2 + 1024)

__global__ __launch_bounds__(256, 2) void proj_kernel(const float* __restrict__ bo,
                                                      float* __restrict__ out) {
    extern __shared__ __half sh[];
    const uint32_t sbase = smem_u32(sh);
    __half* Wot = sh;
    float*  bos = (float*)(sh + 256 * AST);

    const int b   = blockIdx.x;
    const int tid = threadIdx.x;
    const int lane = tid & 31, wid = tid >> 5;
    const int g = lane >> 2, t = lane & 3;
    const int rw0 = wid * 32;

    #pragma unroll
    for (int l = 0; l < 8; l++) {
        const int i = l * 256 + tid;
        const int r = i >> 3, c8 = (i & 7) * 8;
        cpa16(sbase + (r * AST + c8) * 2, g_wot + r * HID + c8);
    }
    if (tid < 64) cpa16(sbase + 256 * AST * 2 + tid * 16, bo + tid * 4);
    CP_COMMIT();

    // o A-fragments from gmem (already normalized fp16)
    const __half* og = g_oh + (size_t)b * QKV_N;
    uint32_t oa[2][4][4];
    #pragma unroll
    for (int mi = 0; mi < 2; mi++) {
        const int r = rw0 + mi * 16 + g;
        #pragma unroll
        for (int kk = 0; kk < 4; kk++) {
            const int kc = kk * 16 + 2 * t;
            oa[mi][kk][0] = __ldg((const uint32_t*)(og + r * HID + kc));
            oa[mi][kk][1] = __ldg((const uint32_t*)(og + (r + 8) * HID + kc));
            oa[mi][kk][2] = __ldg((const uint32_t*)(og + r * HID + kc + 8));
            oa[mi][kk][3] = __ldg((const uint32_t*)(og + (r + 8) * HID + kc + 8));
        }
    }
    CP_WAIT0();
    __syncthreads();

    float* ob = out + (size_t)b * N_OUT * N_OUT;
    #pragma unroll 1
    for (int nc = 0; nc < 4; nc++) {
        float ac[2][8][4];
        #pragma unroll
        for (int mi = 0; mi < 2; mi++)
            #pragma unroll
            for (int j = 0; j < 8; j++)
                #pragma unroll
                for (int q = 0; q < 4; q++) ac[mi][j][q] = 0.0f;
        #pragma unroll
        for (int kk = 0; kk < 4; kk++) {
            const int kc = kk * 16 + 2 * t;
            #pragma unroll
            for (int j = 0; j < 8; j++) {
                uint32_t bw[2];
                const int n = 64 * nc + 8 * j + g;
                bw[0] = *(const uint32_t*)(Wot + n * AST + kc);
                bw[1] = *(const uint32_t*)(Wot + n * AST + kc + 8);
                mma16816(ac[0][j], oa[0][kk], bw);
                mma16816(ac[1][j], oa[1][kk], bw);
            }
        }
        #pragma unroll
        for (int mi = 0; mi < 2; mi++) {
            const int r = rw0 + mi * 16 + g;
            #pragma unroll
            for (int j = 0; j < 8; j++) {
                const int col = 64 * nc + 8 * j + 2 * t;
                const float b0 = bos[col], b1 = bos[col + 1];
                float2 v0, v1;
                v0.x = -fmaxf(ac[mi][j][0] + b0, 0.0f);
                v0.y = -fmaxf(ac[mi][j][1] + b1, 0.0f);
                v1.x = -fmaxf(ac[mi][j][2] + b0, 0.0f);
                v1.y = -fmaxf(ac[mi][j][3] + b1, 0.0f);
                *(float2*)(ob + (size_t)r * N_OUT + col)       = v0;
                *(float2*)(ob + (size_t)(r + 8) * N_OUT + col) = v1;
            }
        }
    }
}

// ------------------------------- launch -------------------------------------
extern "C" void kernel_launch(void* const* d_in, const int* in_sizes, int n_in,
                              void* d_out, int out_size) {
    const float* x    = (const float*)d_in[0];
    const float* ln_g = (const float*)d_in[1];
    const float* ln_b = (const float*)d_in[2];
    const float* Wq   = (const float*)d_in[3];
    const float* bq   = (const float*)d_in[4];
    const float* Wk   = (const float*)d_in[5];
    const float* bk   = (const float*)d_in[6];
    const float* Wv   = (const float*)d_in[7];
    const float* bv   = (const float*)d_in[8];
    const float* Wo   = (const float*)d_in[9];
    const float* bo   = (const float*)d_in[10];
    float* out = (float*)d_out;

    ln_kernel<<<B_DIM, 128>>>(x, ln_g, ln_b);

    dim3 gw(QKV_N / 32, N_IN / 64, 3);
    wsplit<<<gw, 256>>>(Wq, Wk, Wv);
    wot_prep<<<(N_OUT * HID) / 256, 256>>>(Wo);

    cudaFuncSetAttribute(gemm_tc, cudaFuncAttributeMaxDynamicSharedMemorySize, GEMM_SMEM);
    dim3 gg(B_DIM / 128, QKV_N / 128, 3);   // (8, 128, 3)
    gemm_tc<<<gg, 128, GEMM_SMEM>>>(bq, bk, bv);

    cudaFuncSetAttribute(attn_kernel, cudaFuncAttributeMaxDynamicSharedMemorySize, ATTN_SMEM);
    attn_kernel<<<B_DIM, 256, ATTN_SMEM>>>(out);

    cudaFuncSetAttribute(proj_kernel, cudaFuncAttributeMaxDynamicSharedMemorySize, PROJ_SMEM);
    proj_kernel<<<B_DIM, 256, PROJ_SMEM>>>(bo, out);
}

// round 13
// speedup vs baseline: 1.0497x; 1.0497x over previous
#include <cuda_runtime.h>
#include <cuda_fp16.h>
#include <cstdint>

#define B_DIM   1024
#define N_IN    512
#define HID     64
#define N_OUT   256
#define QKV_N   (HID * N_OUT)   // 16384

// ----------------------------- PTX helpers ----------------------------------
__device__ __forceinline__ void mma16816(float* c, const uint32_t* a, const uint32_t* b) {
    asm volatile(
        "mma.sync.aligned.m16n8k16.row.col.f32.f16.f16.f32 "
        "{%0,%1,%2,%3}, {%4,%5,%6,%7}, {%8,%9}, {%0,%1,%2,%3};"
        : "+f"(c[0]), "+f"(c[1]), "+f"(c[2]), "+f"(c[3])
        : "r"(a[0]), "r"(a[1]), "r"(a[2]), "r"(a[3]), "r"(b[0]), "r"(b[1]));
}
__device__ __forceinline__ uint32_t packh2(float x, float y) {
    __half2 h = __floats2half2_rn(x, y);
    return *(uint32_t*)&h;
}
__device__ __forceinline__ uint32_t smem_u32(const void* p) {
    uint32_t a;
    asm("{ .reg .u64 t; cvta.to.shared.u64 t, %1; cvt.u32.u64 %0, t; }" : "=r"(a) : "l"(p));
    return a;
}
__device__ __forceinline__ void ldmx4(uint32_t* r, uint32_t addr) {
    asm volatile("ldmatrix.sync.aligned.m8n8.x4.shared.b16 {%0,%1,%2,%3}, [%4];"
                 : "=r"(r[0]), "=r"(r[1]), "=r"(r[2]), "=r"(r[3]) : "r"(addr));
}
__device__ __forceinline__ void cpa16(uint32_t dst, const void* src) {
    asm volatile("{ .reg .u64 g; cvta.to.global.u64 g, %1; "
                 "cp.async.cg.shared.global [%0], [g], 16; }"
                 :: "r"(dst), "l"(src));
}
#define CP_COMMIT() asm volatile("cp.async.commit_group;" ::: "memory")
#define CP_WAIT1()  asm volatile("cp.async.wait_group 1;" ::: "memory")
#define CP_WAIT0()  asm volatile("cp.async.wait_group 0;" ::: "memory")

// -------------------- scratch (device globals; no allocation) ---------------
__device__ __half g_h[B_DIM * N_IN];              // ln output fp16
__device__ __half g_wt[3ull * QKV_N * N_IN];      // W^T [w][n][k] fp16
__device__ __half g_qh[(size_t)B_DIM * QKV_N];    // (q+bq)*0.125
__device__ __half g_kh[(size_t)B_DIM * QKV_N];
__device__ __half g_vh[(size_t)B_DIM * QKV_N];
__device__ __half g_wot[N_OUT * HID];             // Wo^T [n][d]

// ------------- FUSED prep: wsplit (blocks 0..12287) + ln + wot --------------
// One launch: removes two kernel-boundary gaps; ln/wot ride inside wsplit's
// bandwidth-bound execution. All three pieces are data-independent.
#define WSPLIT_BLOCKS 12288            // 512 n * 8 k * 3 w
#define LN_BLOCKS     1024
#define PREP_BLOCKS   (WSPLIT_BLOCKS + LN_BLOCKS + 64)

__global__ __launch_bounds__(256) void prep_kernel(const float* __restrict__ x,
                                                   const float* __restrict__ gamma,
                                                   const float* __restrict__ beta,
                                                   const float* __restrict__ Wq,
                                                   const float* __restrict__ Wk,
                                                   const float* __restrict__ Wv,
                                                   const float* __restrict__ Wo) {
    const int blk = blockIdx.x;
    const int tid = threadIdx.x;

    if (blk < WSPLIT_BLOCKS) {
        // ---- wsplit: transpose W fp32 [K][N] -> fp16 [N][K] ----
        const int z   = blk / 4096;
        const int rem = blk - z * 4096;
        const int n0  = (rem & 511) * 32;
        const int k0  = (rem >> 9) * 64;
        const float* W = (z == 0) ? Wq : (z == 1) ? Wk : Wv;
        __shared__ float s[64][33];
        #pragma unroll
        for (int i = 0; i < 8; i++) {
            const int k = i * 8 + (tid >> 5);
            const int n = tid & 31;
            s[k][n] = W[(size_t)(k0 + k) * QKV_N + n0 + n];
        }
        __syncthreads();
        const int n  = tid >> 3;
        const int c8 = (tid & 7) * 8;
        __half h8[8];
        #pragma unroll
        for (int j = 0; j < 8; j++) h8[j] = __float2half_rn(s[c8 + j][n]);
        *(uint4*)(g_wt + ((size_t)z * QKV_N + n0 + n) * N_IN + k0 + c8) = *(uint4*)h8;
        return;
    }
    if (blk < WSPLIT_BLOCKS + LN_BLOCKS) {
        // ---- LayerNorm row (threads 0..127 active; rest only sync) ----
        __shared__ float ssum[4], ssq[4];
        const int b = blk - WSPLIT_BLOCKS;
        float4 v = {0.f, 0.f, 0.f, 0.f};
        float s = 0.f, q = 0.f;
        if (tid < 128) {
            v = ((const float4*)(x + (size_t)b * N_IN))[tid];
            s = v.x + v.y + v.z + v.w;
            q = v.x * v.x + v.y * v.y + v.z * v.z + v.w * v.w;
            #pragma unroll
            for (int o = 16; o > 0; o >>= 1) {
                s += __shfl_xor_sync(0xffffffffu, s, o);
                q += __shfl_xor_sync(0xffffffffu, q, o);
            }
            if ((tid & 31) == 0) { ssum[tid >> 5] = s; ssq[tid >> 5] = q; }
        }
        __syncthreads();
        if (tid < 128) {
            s = ssum[0] + ssum[1] + ssum[2] + ssum[3];
            q = ssq[0] + ssq[1] + ssq[2] + ssq[3];
            const float mu   = s * (1.0f / N_IN);
            const float var  = q * (1.0f / N_IN) - mu * mu;
            const float rstd = rsqrtf(var + 1e-5f);
            const float4 g  = ((const float4*)gamma)[tid];
            const float4 be = ((const float4*)beta)[tid];
            uint2 o;
            o.x = packh2((v.x - mu) * rstd * g.x + be.x, (v.y - mu) * rstd * g.y + be.y);
            o.y = packh2((v.z - mu) * rstd * g.z + be.z, (v.w - mu) * rstd * g.w + be.w);
            *(uint2*)(g_h + (size_t)b * N_IN + 4 * tid) = o;
        }
        return;
    }
    // ---- Wo^T fp16: 64 blocks x 256 elements ----
    const int idx = (blk - WSPLIT_BLOCKS - LN_BLOCKS) * 256 + tid;
    const int n = idx >> 6, d = idx & 63;
    g_wot[idx] = __float2half_rn(Wo[d * N_OUT + n]);
}

// ---------- QKV GEMM (R8 best): 128x128 CTA, 4 warps @ 64x64, 3-stage -------
#define GST   72                                  // smem row stride (halfs)
#define STAGE (256 * GST)                         // A(128) + B(128) rows
#define GEMM_SMEM (3 * STAGE * 2)                 // 110592 bytes

__global__ __launch_bounds__(128, 2) void gemm_tc(const float* __restrict__ bq,
                                                  const float* __restrict__ bk,
                                                  const float* __restrict__ bv) {
    extern __shared__ __half sh[];
    const uint32_t sbase = smem_u32(sh);
    const int tid = threadIdx.x;
    const int lane = tid & 31, wid = tid >> 5;
    const int g = lane >> 2, t = lane & 3;
    const int wm = wid >> 1, wn = wid & 1;        // 2m x 2n warps, 64x64 tile
    const int m0 = blockIdx.x * 128;
    const int n0 = blockIdx.y * 128;
    const int w  = blockIdx.z;
    const float* bias = (w == 0) ? bq : (w == 1) ? bk : bv;
    __half* outh = (w == 0) ? g_qh : (w == 1) ? g_kh : g_vh;
    const __half* wt = g_wt + (size_t)w * QKV_N * N_IN;

    float acc[4][8][4];
    #pragma unroll
    for (int i = 0; i < 4; i++)
        #pragma unroll
        for (int j = 0; j < 8; j++)
            #pragma unroll
            for (int q = 0; q < 4; q++) acc[i][j][q] = 0.0f;

    auto load_chunk = [&](int c, int st) {
        const int kt = c * 64;
        const uint32_t s0 = sbase + st * STAGE * 2;
        #pragma unroll
        for (int l = 0; l < 8; l++) {
            const int i = l * 128 + tid;
            const int r = i >> 3, c8 = (i & 7) * 8;
            cpa16(s0 + (r * GST + c8) * 2, g_h + (size_t)(m0 + r) * N_IN + kt + c8);
        }
        #pragma unroll
        for (int l = 0; l < 8; l++) {
            const int i = l * 128 + tid;
            const int r = i >> 3, c8 = (i & 7) * 8;
            cpa16(s0 + ((128 + r) * GST + c8) * 2, wt + (size_t)(n0 + r) * N_IN + kt + c8);
        }
    };

    const int aRow = wm * 64 + (lane & 15);
    const int aCol = (lane >> 4) * 8;
    const int bRow = 128 + wn * 64 + (lane & 7) + ((lane >> 4) & 1) * 8;
    const int bCol = ((lane >> 3) & 1) * 8;

    load_chunk(0, 0); CP_COMMIT();
    load_chunk(1, 1); CP_COMMIT();

    #pragma unroll 1
    for (int c = 0; c < 8; c++) {
        const int st = c % 3;
        if (c < 7) CP_WAIT1(); else CP_WAIT0();   // tail: drain fully
        __syncthreads();
        if (c + 2 < 8) { load_chunk(c + 2, (c + 2) % 3); CP_COMMIT(); }

        const uint32_t s0 = sbase + st * STAGE * 2;
        #pragma unroll
        for (int kk = 0; kk < 4; kk++) {
            const int kc = kk * 16;
            uint32_t ah[4][4], bh[4][4];
            #pragma unroll
            for (int mi = 0; mi < 4; mi++)
                ldmx4(ah[mi], s0 + ((aRow + mi * 16) * GST + kc + aCol) * 2);
            #pragma unroll
            for (int nb = 0; nb < 4; nb++)
                ldmx4(bh[nb], s0 + ((bRow + nb * 16) * GST + kc + bCol) * 2);
            #pragma unroll
            for (int mi = 0; mi < 4; mi++)
                #pragma unroll
                for (int nj = 0; nj < 8; nj++)
                    mma16816(acc[mi][nj], ah[mi], &bh[nj >> 1][(nj & 1) * 2]);
        }
    }

    const float scale = (w == 0) ? 0.125f : 1.0f;
    #pragma unroll
    for (int mi = 0; mi < 4; mi++) {
        const int r = m0 + wm * 64 + mi * 16 + g;
        #pragma unroll
        for (int nj = 0; nj < 8; nj++) {
            const int col = n0 + wn * 64 + nj * 8 + 2 * t;
            const float b0 = __ldg(bias + col), b1 = __ldg(bias + col + 1);
            *(uint32_t*)(outh + (size_t)r * QKV_N + col) =
                packh2((acc[mi][nj][0] + b0) * scale, (acc[mi][nj][1] + b1) * scale);
            *(uint32_t*)(outh + (size_t)(r + 8) * QKV_N + col) =
                packh2((acc[mi][nj][2] + b0) * scale, (acc[mi][nj][3] + b1) * scale);
        }
    }
}

// --------------- fused attention + output projection (mma.sync) -------------
// R11 version verbatim (best measured: 308.3).
#define AST 72
#define VST 266
#define OFF_K  0
#define OFF_VT (256 * AST)
#define OFF_WO (256 * AST + 64 * VST)
#define OFF_BO (OFF_WO + 256 * AST)
#define ATTN_SMEM (OFF_BO * 2 + 256 * 4)

__global__ __launch_bounds__(256, 1) void attn_kernel(const float* __restrict__ bo,
                                                      float* __restrict__ out) {
    extern __shared__ __half sh[];
    const uint32_t sbase = smem_u32(sh);
    __half* Ks  = sh + OFF_K;
    __half* Vt  = sh + OFF_VT;
    __half* Wot = sh + OFF_WO;
    float*  bos = (float*)(sh + OFF_BO);

    const int b   = blockIdx.x;
    const int tid = threadIdx.x;
    const int lane = tid & 31, wid = tid >> 5;
    const int g = lane >> 2, t = lane & 3;
    const int rw0 = wid * 32;

    const __half* qg = g_qh + (size_t)b * QKV_N;
    const __half* kg = g_kh + (size_t)b * QKV_N;
    const __half* vg = g_vh + (size_t)b * QKV_N;

    // ---- stage: V LDGs first (batched), then async K/Wot/bo underneath ----
    uint4 vbuf[8];
    #pragma unroll
    for (int l = 0; l < 8; l++) {
        const int i = l * 256 + tid;
        const int r = i >> 3, c8 = (i & 7) * 8;
        vbuf[l] = *(const uint4*)(vg + r * HID + c8);
    }
    #pragma unroll
    for (int l = 0; l < 8; l++) {
        const int i = l * 256 + tid;
        const int r = i >> 3, c8 = (i & 7) * 8;
        cpa16(sbase + (OFF_K + r * AST + c8) * 2, kg + r * HID + c8);
        cpa16(sbase + (OFF_WO + r * AST + c8) * 2, g_wot + r * HID + c8);
    }
    if (tid < 64) cpa16(sbase + OFF_BO * 2 + tid * 16, bo + tid * 4);
    CP_COMMIT();
    // V transpose: [kv][d] -> Vt[d][kv]
    #pragma unroll
    for (int l = 0; l < 8; l++) {
        const int i = l * 256 + tid;
        const int r = i >> 3, c8 = (i & 7) * 8;
        const __half* hp = (const __half*)&vbuf[l];
        #pragma unroll
        for (int j = 0; j < 8; j++) Vt[(c8 + j) * VST + r] = hp[j];
    }
    // ---- Q A-fragments straight from gmem (same values as smem path) ----
    uint32_t aq[2][4][4];
    #pragma unroll
    for (int mi = 0; mi < 2; mi++) {
        const int r = rw0 + mi * 16 + g;
        #pragma unroll
        for (int kk = 0; kk < 4; kk++) {
            const int kc = kk * 16 + 2 * t;
            aq[mi][kk][0] = __ldg((const uint32_t*)(qg + r * HID + kc));
            aq[mi][kk][1] = __ldg((const uint32_t*)(qg + (r + 8) * HID + kc));
            aq[mi][kk][2] = __ldg((const uint32_t*)(qg + r * HID + kc + 8));
            aq[mi][kk][3] = __ldg((const uint32_t*)(qg + (r + 8) * HID + kc + 8));
        }
    }
    CP_WAIT0();
    __syncthreads();

    float oc[2][8][4];
    #pragma unroll
    for (int mi = 0; mi < 2; mi++)
        #pragma unroll
        for (int j = 0; j < 8; j++)
            #pragma unroll
            for (int q = 0; q < 4; q++) oc[mi][j][q] = 0.0f;
    float lp[2][2] = {{0.f, 0.f}, {0.f, 0.f}};

    #pragma unroll 1
    for (int c = 0; c < 4; c++) {
        float sc[2][8][4];
        #pragma unroll
        for (int mi = 0; mi < 2; mi++)
            #pragma unroll
            for (int j = 0; j < 8; j++)
                #pragma unroll
                for (int q = 0; q < 4; q++) sc[mi][j][q] = 0.0f;

        #pragma unroll
        for (int kk = 0; kk < 4; kk++) {
            const int kc = kk * 16 + 2 * t;
            #pragma unroll
            for (int j = 0; j < 8; j++) {
                uint32_t bk[2];
                const int kv = 64 * c + 8 * j + g;
                bk[0] = *(const uint32_t*)(Ks + kv * AST + kc);
                bk[1] = *(const uint32_t*)(Ks + kv * AST + kc + 8);
                mma16816(sc[0][j], aq[0][kk], bk);
                mma16816(sc[1][j], aq[1][kk], bk);
            }
        }

        uint32_t pa[2][4][4];
        #pragma unroll
        for (int mi = 0; mi < 2; mi++) {
            #pragma unroll
            for (int j = 0; j < 8; j++) {
                float e0 = __expf(sc[mi][j][0]);
                float e1 = __expf(sc[mi][j][1]);
                float e2 = __expf(sc[mi][j][2]);
                float e3 = __expf(sc[mi][j][3]);
                lp[mi][0] += e0 + e1;
                lp[mi][1] += e2 + e3;
                const int kk2 = j >> 1, hi = j & 1;
                pa[mi][kk2][hi * 2 + 0] = packh2(e0, e1);
                pa[mi][kk2][hi * 2 + 1] = packh2(e2, e3);
            }
        }

        #pragma unroll
        for (int kk2 = 0; kk2 < 4; kk2++) {
            const int kvc = 64 * c + kk2 * 16 + 2 * t;
            #pragma unroll
            for (int j2 = 0; j2 < 8; j2++) {
                uint32_t bv[2];
                const int d = 8 * j2 + g;
                bv[0] = *(const uint32_t*)(Vt + d * VST + kvc);
                bv[1] = *(const uint32_t*)(Vt + d * VST + kvc + 8);
                mma16816(oc[0][j2], pa[0][kk2], bv);
                mma16816(oc[1][j2], pa[1][kk2], bv);
            }
        }
    }

    #pragma unroll
    for (int mi = 0; mi < 2; mi++)
        #pragma unroll
        for (int h = 0; h < 2; h++) {
            float l = lp[mi][h];
            l += __shfl_xor_sync(0xffffffffu, l, 1);
            l += __shfl_xor_sync(0xffffffffu, l, 2);
            lp[mi][h] = 1.0f / l;
        }
    uint32_t oa[2][4][4];
    #pragma unroll
    for (int mi = 0; mi < 2; mi++)
        #pragma unroll
        for (int kk = 0; kk < 4; kk++) {
            const int j2a = 2 * kk, j2b = 2 * kk + 1;
            oa[mi][kk][0] = packh2(oc[mi][j2a][0] * lp[mi][0], oc[mi][j2a][1] * lp[mi][0]);
            oa[mi][kk][1] = packh2(oc[mi][j2a][2] * lp[mi][1], oc[mi][j2a][3] * lp[mi][1]);
            oa[mi][kk][2] = packh2(oc[mi][j2b][0] * lp[mi][0], oc[mi][j2b][1] * lp[mi][0]);
            oa[mi][kk][3] = packh2(oc[mi][j2b][2] * lp[mi][1], oc[mi][j2b][3] * lp[mi][1]);
        }

    float* ob = out + (size_t)b * N_OUT * N_OUT;
    #pragma unroll 1
    for (int nc = 0; nc < 4; nc++) {
        float ac[2][8][4];
        #pragma unroll
        for (int mi = 0; mi < 2; mi++)
            #pragma unroll
            for (int j = 0; j < 8; j++)
                #pragma unroll
                for (int q = 0; q < 4; q++) ac[mi][j][q] = 0.0f;
        #pragma unroll
        for (int kk = 0; kk < 4; kk++) {
            const int kc = kk * 16 + 2 * t;
            #pragma unroll
            for (int j = 0; j < 8; j++) {
                uint32_t bw[2];
                const int n = 64 * nc + 8 * j + g;
                bw[0] = *(const uint32_t*)(Wot + n * AST + kc);
                bw[1] = *(const uint32_t*)(Wot + n * AST + kc + 8);
                mma16816(ac[0][j], oa[0][kk], bw);
                mma16816(ac[1][j], oa[1][kk], bw);
            }
        }
        #pragma unroll
        for (int mi = 0; mi < 2; mi++) {
            const int r = rw0 + mi * 16 + g;
            #pragma unroll
            for (int j = 0; j < 8; j++) {
                const int col = 64 * nc + 8 * j + 2 * t;
                const float b0 = bos[col], b1 = bos[col + 1];
                float2 v0, v1;
                v0.x = -fmaxf(ac[mi][j][0] + b0, 0.0f);
                v0.y = -fmaxf(ac[mi][j][1] + b1, 0.0f);
                v1.x = -fmaxf(ac[mi][j][2] + b0, 0.0f);
                v1.y = -fmaxf(ac[mi][j][3] + b1, 0.0f);
                *(float2*)(ob + (size_t)r * N_OUT + col)       = v0;
                *(float2*)(ob + (size_t)(r + 8) * N_OUT + col) = v1;
            }
        }
    }
}

// ------------------------------- launch -------------------------------------
extern "C" void kernel_launch(void* const* d_in, const int* in_sizes, int n_in,
                              void* d_out, int out_size) {
    const float* x    = (const float*)d_in[0];
    const float* ln_g = (const float*)d_in[1];
    const float* ln_b = (const float*)d_in[2];
    const float* Wq   = (const float*)d_in[3];
    const float* bq   = (const float*)d_in[4];
    const float* Wk   = (const float*)d_in[5];
    const float* bk   = (const float*)d_in[6];
    const float* Wv   = (const float*)d_in[7];
    const float* bv   = (const float*)d_in[8];
    const float* Wo   = (const float*)d_in[9];
    const float* bo   = (const float*)d_in[10];
    float* out = (float*)d_out;

    prep_kernel<<<PREP_BLOCKS, 256>>>(x, ln_g, ln_b, Wq, Wk, Wv, Wo);

    cudaFuncSetAttribute(gemm_tc, cudaFuncAttributeMaxDynamicSharedMemorySize, GEMM_SMEM);
    dim3 gg(B_DIM / 128, QKV_N / 128, 3);   // (8, 128, 3)
    gemm_tc<<<gg, 128, GEMM_SMEM>>>(bq, bk, bv);

    cudaFuncSetAttribute(attn_kernel, cudaFuncAttributeMaxDynamicSharedMemorySize, ATTN_SMEM);
    attn_kernel<<<B_DIM, 256, ATTN_SMEM>>>(bo, out);
}